// round 9
// baseline (speedup 1.0000x reference)
#include <cuda_runtime.h>

// VisibilityHeatmap: per (b,k) keypoint, NDC coord -> pixel index, gather ONE
// heatmap value, threshold, broadcast mask to both coord lanes.
//
// coords [B=32,K=64,2] f32, heatmaps [B,K,256,256] f32, out [B,K,2] f32.
// Latency-bound micro-kernel: 2048 independent gathers, ~260KB touched.
//
// Tuning history (ncu kernel dur / harness wall):
//   branchy   8x256 : 7.7-8.2us / 4.64us
//   branchless 32x64 : 5.31us
//   + streaming ld/st: 5.15us / 4.61us  <- R8 best (committed)
// This round: replace the 4-op min/max clamp with 2-op AND-255 masking.
// Invalid lanes only need an IN-BOUNDS address (value is masked out);
// valid lanes have u,v in [0,256) so AND is the identity.

#define THRESHOLD 0.4f

__global__ void __launch_bounds__(64, 1)
vis_heatmap_kernel(const float* __restrict__ coords,
                   const float* __restrict__ heatmaps,
                   float* __restrict__ out)
{
    int i = blockIdx.x * 64 + threadIdx.x;   // exact fit (2048 = 32*64)

    // Coalesced vectorized coord load, streaming policy (read-once data)
    float2 c = __ldcs(reinterpret_cast<const float2*>(coords) + i);

    // ndc -> pixel via single FMA each; truncate toward zero (.astype(int32))
    int u = (int)__fmaf_rn(c.x, 128.0f, 128.0f);   // (x+1)*0.5*256
    int v = (int)__fmaf_rn(c.y, 128.0f, 128.0f);

    // valid iff 0 <= u < 256 and 0 <= v < 256 (one unsigned compare each)
    bool valid = ((unsigned)u < 256u) & ((unsigned)v < 256u);

    // Always load from an in-bounds address: AND-255 instead of clamp.
    // Valid lanes: identity. Invalid lanes: arbitrary in-bounds element,
    // value discarded by the mask below.
    unsigned idx = ((unsigned)i << 16)
                 | (((unsigned)v & 255u) << 8)
                 | ((unsigned)u & 255u);
    float val = __ldg(&heatmaps[idx]);   // .nc: keep heatmap lines L2-warm

    float m = (valid & (val > THRESHOLD)) ? 1.0f : 0.0f;

    // Coalesced vectorized store, streaming policy (write-once output)
    __stcs(reinterpret_cast<float2*>(out) + i, make_float2(m, m));
}

extern "C" void kernel_launch(void* const* d_in, const int* in_sizes, int n_in,
                              void* d_out, int out_size)
{
    const float* coords   = (const float*)d_in[0];
    const float* heatmaps = (const float*)d_in[1];
    float* out = (float*)d_out;

    int n = in_sizes[0] / 2;         // B*K = 2048 keypoints
    int blocks = (n + 63) / 64;      // = 32 CTAs x 64 threads
    vis_heatmap_kernel<<<blocks, 64>>>(coords, heatmaps, out);
}

// round 10
// speedup vs baseline: 1.0069x; 1.0069x over previous
#include <cuda_runtime.h>

// VisibilityHeatmap — FINAL (confirmation re-bench of R8 champion).
//
// Per (b,k) keypoint: NDC coord -> pixel index, gather ONE heatmap value,
// threshold, broadcast mask to both coord lanes.
// coords [B=32,K=64,2] f32, heatmaps [B,K,256,256] f32, out [B,K,2] f32.
//
// Latency-bound micro-kernel: 2048 independent gathers, ~260KB touched of
// 512MB (L2-resident across graph replays). Converged configuration:
//   - 32 CTAs x 64 threads (shape optimum: 8x256=5.8, 64x32=5.47,
//     32x64=5.15us ncu dur)
//   - branchless body, 16 regs, no BSSY/BSYNC
//   - FMA ndc->pixel, unsigned range checks, clamp + always-load + mask
//   - streaming ld (.cs) for read-once coords, streaming st (.cs) for
//     write-once output; gather via __ldg to keep heatmap lines L2-warm
// All pipes <1% in ncu; kernel = launch overhead + one dependent gather
// round trip. No roofline headroom remains.

#define THRESHOLD 0.4f

__global__ void __launch_bounds__(64, 1)
vis_heatmap_kernel(const float* __restrict__ coords,
                   const float* __restrict__ heatmaps,
                   float* __restrict__ out)
{
    int i = blockIdx.x * 64 + threadIdx.x;   // exact fit (2048 = 32*64)

    // Coalesced vectorized coord load, streaming policy (read-once data)
    float2 c = __ldcs(reinterpret_cast<const float2*>(coords) + i);

    // ndc -> pixel via single FMA each; truncate toward zero (.astype(int32))
    int u = (int)__fmaf_rn(c.x, 128.0f, 128.0f);   // (x+1)*0.5*256
    int v = (int)__fmaf_rn(c.y, 128.0f, 128.0f);

    // valid iff 0 <= u < 256 and 0 <= v < 256 (one unsigned compare each)
    bool valid = ((unsigned)u < 256u) & ((unsigned)v < 256u);

    // Clamp and ALWAYS load (branchless; reference also clamps then masks).
    int uc = min(max(u, 0), 255);
    int vc = min(max(v, 0), 255);
    unsigned idx = ((unsigned)i << 16) | ((unsigned)vc << 8) | (unsigned)uc;
    float val = __ldg(&heatmaps[idx]);   // .nc: keep heatmap lines L2-warm

    float m = (valid & (val > THRESHOLD)) ? 1.0f : 0.0f;

    // Coalesced vectorized store, streaming policy (write-once output)
    __stcs(reinterpret_cast<float2*>(out) + i, make_float2(m, m));
}

extern "C" void kernel_launch(void* const* d_in, const int* in_sizes, int n_in,
                              void* d_out, int out_size)
{
    const float* coords   = (const float*)d_in[0];
    const float* heatmaps = (const float*)d_in[1];
    float* out = (float*)d_out;

    int n = in_sizes[0] / 2;         // B*K = 2048 keypoints
    int blocks = (n + 63) / 64;      // = 32 CTAs x 64 threads
    vis_heatmap_kernel<<<blocks, 64>>>(coords, heatmaps, out);
}